// round 2
// baseline (speedup 1.0000x reference)
#include <cuda_runtime.h>

#define NB 32
#define LL 1024
#define TT 64

__global__ __launch_bounds__(256, 1)
void crf_forward_kernel(const float* __restrict__ logits,     // [B,L,T]
                        const float* __restrict__ trans,      // [T,T]
                        const float* __restrict__ start_s,    // [T]
                        const float* __restrict__ end_s,      // [T]
                        const int* __restrict__ mask,         // [B,L] bool stored as int32
                        float* __restrict__ out)              // [B]
{
    const int b    = blockIdx.x;
    const int tid  = threadIdx.x;
    const int j    = tid >> 2;   // state 0..63
    const int part = tid & 3;    // i-range partition 0..3

    __shared__ __align__(16) float beta[2][TT];
    __shared__ int s_red[8];
    __shared__ int s_end;

    // ---- end_idx = (count of nonzero mask entries) - 1 ; mask is int32 ----
    {
        const int4* mb = reinterpret_cast<const int4*>(mask + (size_t)b * LL);
        int4 m4 = mb[tid];                       // 256 threads * 4 ints = 1024
        int cnt = (m4.x != 0) + (m4.y != 0) + (m4.z != 0) + (m4.w != 0);
        #pragma unroll
        for (int o = 16; o > 0; o >>= 1) cnt += __shfl_xor_sync(0xffffffffu, cnt, o);
        if ((tid & 31) == 0) s_red[tid >> 5] = cnt;
        __syncthreads();
        if (tid == 0) {
            int tot = 0;
            #pragma unroll
            for (int w = 0; w < 8; ++w) tot += s_red[w];
            s_end = tot - 1;
        }
        __syncthreads();
    }
    const int endi = s_end;

    // ---- E column slice in registers: e[k] = exp(trans[part*16+k][j]) ----
    float e[16];
    #pragma unroll
    for (int k = 0; k < 16; ++k)
        e[k] = __expf(__ldg(&trans[(part * 16 + k) * TT + j]));

    const float* lg = logits + (size_t)b * LL * TT + j;

    float endraw = 0.0f;
    float offset = 0.0f;
    if (part == 0) {
        endraw = __ldg(&end_s[j]);
        float a0 = lg[0] + __ldg(&start_s[j]);
        if (endi == 0) a0 += endraw;
        beta[0][j] = __expf(a0);
    }
    __syncthreads();

    int buf = 0;

    auto step = [&](float graw, int t) {
        const float4* bv = reinterpret_cast<const float4*>(&beta[buf][part * 16]);
        float4 x0 = bv[0], x1 = bv[1], x2 = bv[2], x3 = bv[3];

        float a0 = x0.x * e[0];
        float a1 = x0.y * e[1];
        float a2 = x0.z * e[2];
        float a3 = x0.w * e[3];
        a0 = fmaf(x1.x, e[4],  a0);
        a1 = fmaf(x1.y, e[5],  a1);
        a2 = fmaf(x1.z, e[6],  a2);
        a3 = fmaf(x1.w, e[7],  a3);
        a0 = fmaf(x2.x, e[8],  a0);
        a1 = fmaf(x2.y, e[9],  a1);
        a2 = fmaf(x2.z, e[10], a2);
        a3 = fmaf(x2.w, e[11], a3);
        a0 = fmaf(x3.x, e[12], a0);
        a1 = fmaf(x3.y, e[13], a1);
        a2 = fmaf(x3.z, e[14], a2);
        a3 = fmaf(x3.w, e[15], a3);
        float s = (a0 + a1) + (a2 + a3);
        s += __shfl_xor_sync(0xffffffffu, s, 1);
        s += __shfl_xor_sync(0xffffffffu, s, 2);

        const bool rn = ((t & 3) == 0);   // renormalize every 4 steps
        float S = 1.0f;
        if (rn) {
            float ls = ((x0.x + x0.y) + (x0.z + x0.w))
                     + ((x1.x + x1.y) + (x1.z + x1.w))
                     + ((x2.x + x2.y) + (x2.z + x2.w))
                     + ((x3.x + x3.y) + (x3.z + x3.w));
            ls += __shfl_xor_sync(0xffffffffu, ls, 1);
            ls += __shfl_xor_sync(0xffffffffu, ls, 2);
            S = ls;
        }

        if (part == 0) {
            float gg = graw;
            if (t == endi) gg += endraw;
            float v = s * __expf(gg);
            if (rn) {
                v *= __frcp_rn(S);
                offset += __logf(S);
            }
            beta[buf ^ 1][j] = v;
        }
        buf ^= 1;
        __syncthreads();
    };

    // ---- main chain with distance-4 register prefetch of raw logits ----
    float g0 = 0.f, g1 = 0.f, g2 = 0.f, g3 = 0.f;
    if (part == 0 && endi >= 1) {
        g0 = lg[(size_t)min(1, endi) * TT];
        g1 = lg[(size_t)min(2, endi) * TT];
        g2 = lg[(size_t)min(3, endi) * TT];
        g3 = lg[(size_t)min(4, endi) * TT];
    }

    int t = 1;
    while (t <= endi) {
        step(g0, t);
        if (part == 0) g0 = lg[(size_t)min(t + 4, endi) * TT];
        ++t; if (t > endi) break;
        step(g1, t);
        if (part == 0) g1 = lg[(size_t)min(t + 4, endi) * TT];
        ++t; if (t > endi) break;
        step(g2, t);
        if (part == 0) g2 = lg[(size_t)min(t + 4, endi) * TT];
        ++t; if (t > endi) break;
        step(g3, t);
        if (part == 0) g3 = lg[(size_t)min(t + 4, endi) * TT];
        ++t;
    }

    // ---- final: out[b] = offset + log(sum_j beta[j]) ----
    {
        const float4* bv = reinterpret_cast<const float4*>(&beta[buf][part * 16]);
        float4 x0 = bv[0], x1 = bv[1], x2 = bv[2], x3 = bv[3];
        float ls = ((x0.x + x0.y) + (x0.z + x0.w))
                 + ((x1.x + x1.y) + (x1.z + x1.w))
                 + ((x2.x + x2.y) + (x2.z + x2.w))
                 + ((x3.x + x3.y) + (x3.z + x3.w));
        ls += __shfl_xor_sync(0xffffffffu, ls, 1);
        ls += __shfl_xor_sync(0xffffffffu, ls, 2);
        if (tid == 0) out[b] = offset + __logf(ls);
    }
}

extern "C" void kernel_launch(void* const* d_in, const int* in_sizes, int n_in,
                              void* d_out, int out_size) {
    const float* logits        = (const float*)d_in[0];
    const float* transitions   = (const float*)d_in[1];
    const float* start_states  = (const float*)d_in[2];
    const float* end_states    = (const float*)d_in[3];
    const int*   mask          = (const int*)d_in[4];
    float* out = (float*)d_out;
    (void)in_sizes; (void)n_in; (void)out_size;

    crf_forward_kernel<<<NB, 256>>>(logits, transitions, start_states,
                                    end_states, mask, out);
}

// round 3
// speedup vs baseline: 1.5399x; 1.5399x over previous
#include <cuda_runtime.h>

#define NB 32
#define LL 1024
#define TT 64

__global__ __launch_bounds__(128, 1)
void crf_forward_kernel(const float* __restrict__ logits,     // [B,L,T]
                        const float* __restrict__ trans,      // [T,T]
                        const float* __restrict__ start_s,    // [T]
                        const float* __restrict__ end_s,      // [T]
                        const int* __restrict__ mask,         // [B,L] bool as int32
                        float* __restrict__ out)              // [B]
{
    const int b    = blockIdx.x;
    const int tid  = threadIdx.x;
    const int j    = tid >> 1;   // output state 0..63
    const int part = tid & 1;    // input-half 0..1

    // beta[buf][0..63] is live data; [64..127] is a duplicate-write scratch
    // area so BOTH part-halves can store unconditionally (no divergent branch).
    __shared__ __align__(16) float beta[2][128];
    __shared__ int s_red[4];
    __shared__ int s_end;

    // ---- end_idx = count(mask != 0) - 1 ; mask stored as int32 ----
    {
        const int4* mb = reinterpret_cast<const int4*>(mask + (size_t)b * LL);
        int4 a = mb[tid * 2], c = mb[tid * 2 + 1];   // 128 thr * 8 ints = 1024
        int cnt = (a.x != 0) + (a.y != 0) + (a.z != 0) + (a.w != 0)
                + (c.x != 0) + (c.y != 0) + (c.z != 0) + (c.w != 0);
        #pragma unroll
        for (int o = 16; o > 0; o >>= 1) cnt += __shfl_xor_sync(0xffffffffu, cnt, o);
        if ((tid & 31) == 0) s_red[tid >> 5] = cnt;
        __syncthreads();
        if (tid == 0)
            s_end = (s_red[0] + s_red[1] + s_red[2] + s_red[3]) - 1;
        __syncthreads();
    }
    const int endi = s_end;

    // ---- E half-column in registers: e[k] = exp(trans[part*32+k][j]) ----
    float e[32];
    #pragma unroll
    for (int k = 0; k < 32; ++k)
        e[k] = __expf(__ldg(&trans[(part * 32 + k) * TT + j]));

    const float* lg = logits + (size_t)b * LL * TT + j;
    const float endraw = __ldg(&end_s[j]);

    // ---- init: v0 = exp(logits[0] + start) (end folded if endi==0) ----
    {
        float a0 = lg[0] + __ldg(&start_s[j]);
        a0 += (endi == 0) ? endraw : 0.0f;
        beta[0][j + part * 64] = __expf(a0);
    }
    __syncthreads();

    int buf = 0;
    float offset = 0.0f, comp = 0.0f;   // Kahan-accumulated log normalizer

    auto step = [&](float graw, int t) {
        const float4* bv = reinterpret_cast<const float4*>(&beta[buf][part * 32]);
        float4 x0 = bv[0], x1 = bv[1], x2 = bv[2], x3 = bv[3];
        float4 x4 = bv[4], x5 = bv[5], x6 = bv[6], x7 = bv[7];
        const float b0 = beta[buf][0];          // broadcast, all threads

        // off-critical-path MUFU work
        const float r  = __frcp_rn(b0);
        const float lb = __logf(b0);
        const float eg = __expf(graw + ((t == endi) ? endraw : 0.0f));

        // 32-term dot in 4 accumulator chains
        float a0 = x0.x * e[0];
        float a1 = x0.y * e[1];
        float a2 = x0.z * e[2];
        float a3 = x0.w * e[3];
        a0 = fmaf(x1.x, e[4],  a0);  a1 = fmaf(x1.y, e[5],  a1);
        a2 = fmaf(x1.z, e[6],  a2);  a3 = fmaf(x1.w, e[7],  a3);
        a0 = fmaf(x2.x, e[8],  a0);  a1 = fmaf(x2.y, e[9],  a1);
        a2 = fmaf(x2.z, e[10], a2);  a3 = fmaf(x2.w, e[11], a3);
        a0 = fmaf(x3.x, e[12], a0);  a1 = fmaf(x3.y, e[13], a1);
        a2 = fmaf(x3.z, e[14], a2);  a3 = fmaf(x3.w, e[15], a3);
        a0 = fmaf(x4.x, e[16], a0);  a1 = fmaf(x4.y, e[17], a1);
        a2 = fmaf(x4.z, e[18], a2);  a3 = fmaf(x4.w, e[19], a3);
        a0 = fmaf(x5.x, e[20], a0);  a1 = fmaf(x5.y, e[21], a1);
        a2 = fmaf(x5.z, e[22], a2);  a3 = fmaf(x5.w, e[23], a3);
        a0 = fmaf(x6.x, e[24], a0);  a1 = fmaf(x6.y, e[25], a1);
        a2 = fmaf(x6.z, e[26], a2);  a3 = fmaf(x6.w, e[27], a3);
        a0 = fmaf(x7.x, e[28], a0);  a1 = fmaf(x7.y, e[29], a1);
        a2 = fmaf(x7.z, e[30], a2);  a3 = fmaf(x7.w, e[31], a3);
        float s = (a0 + a1) + (a2 + a3);
        s += __shfl_xor_sync(0xffffffffu, s, 1);   // pair (j,0)+(j,1)

        // normalized write — unconditional, disjoint slots per part
        beta[buf ^ 1][j + part * 64] = s * r * eg;

        // Kahan: offset += log(b0)
        float y = lb - comp;
        float tt = offset + y;
        comp = (tt - offset) - y;
        offset = tt;

        buf ^= 1;
        __syncthreads();
    };

    // ---- main chain, 4-deep register prefetch of raw logits ----
    float g0 = 0.f, g1 = 0.f, g2 = 0.f, g3 = 0.f;
    if (endi >= 1) {
        g0 = lg[(size_t)min(1, endi) * TT];
        g1 = lg[(size_t)min(2, endi) * TT];
        g2 = lg[(size_t)min(3, endi) * TT];
        g3 = lg[(size_t)min(4, endi) * TT];
    }

    int t = 1;
    while (t <= endi) {
        step(g0, t);
        g0 = lg[(size_t)min(t + 4, endi) * TT];
        ++t; if (t > endi) break;
        step(g1, t);
        g1 = lg[(size_t)min(t + 4, endi) * TT];
        ++t; if (t > endi) break;
        step(g2, t);
        g2 = lg[(size_t)min(t + 4, endi) * TT];
        ++t; if (t > endi) break;
        step(g3, t);
        g3 = lg[(size_t)min(t + 4, endi) * TT];
        ++t;
    }

    // ---- final: out[b] = offset + log(sum_j beta[j]) ----
    {
        const float4* bv = reinterpret_cast<const float4*>(&beta[buf][part * 32]);
        float ls = 0.0f;
        #pragma unroll
        for (int q = 0; q < 8; ++q) {
            float4 x = bv[q];
            ls += (x.x + x.y) + (x.z + x.w);
        }
        ls += __shfl_xor_sync(0xffffffffu, ls, 1);
        if (tid == 0) out[b] = offset + __logf(ls);
    }
}

extern "C" void kernel_launch(void* const* d_in, const int* in_sizes, int n_in,
                              void* d_out, int out_size) {
    const float* logits        = (const float*)d_in[0];
    const float* transitions   = (const float*)d_in[1];
    const float* start_states  = (const float*)d_in[2];
    const float* end_states    = (const float*)d_in[3];
    const int*   mask          = (const int*)d_in[4];
    float* out = (float*)d_out;
    (void)in_sizes; (void)n_in; (void)out_size;

    crf_forward_kernel<<<NB, 128>>>(logits, transitions, start_states,
                                    end_states, mask, out);
}

// round 4
// speedup vs baseline: 2.9307x; 1.9031x over previous
#include <cuda_runtime.h>

#define NB 32
#define LL 1024
#define TT 64

#define FMA2(d,a,b,c) asm("fma.rn.f32x2 %0, %1, %2, %3;" : "=l"(d) : "l"(a), "l"(b), "l"(c))
#define MUL2(d,a,b)   asm("mul.rn.f32x2 %0, %1, %2;"     : "=l"(d) : "l"(a), "l"(b))
#define UNPACK2(lo,hi,v) asm("mov.b64 {%0,%1}, %2;" : "=f"(lo), "=f"(hi) : "l"(v))
#define PACK2(v,lo,hi)   asm("mov.b64 %0, {%1,%2};" : "=l"(v) : "f"(lo), "f"(hi))

__global__ __launch_bounds__(128, 1)
void crf_forward_kernel(const float* __restrict__ logits,     // [B,L,T]
                        const float* __restrict__ trans,      // [T,T]
                        const float* __restrict__ start_s,    // [T]
                        const float* __restrict__ end_s,      // [T]
                        const int* __restrict__ mask,         // [B,L] bool as int32
                        float* __restrict__ out)              // [B]
{
    const int b    = blockIdx.x;
    const int tid  = threadIdx.x;
    const int j    = tid >> 1;   // output state 0..63
    const int part = tid & 1;    // input-half 0..1

    // live vector at slots [0..31] and [40..71] (8-float pad kills the
    // 2-way bank conflict between the two broadcast groups);
    // [128..191] = duplicate-write scratch for part==1 (branchless stores).
    __shared__ __align__(16) float beta[2][192];
    __shared__ int s_red[4];
    __shared__ int s_end;

    // ---- end_idx = count(mask != 0) - 1 ; mask stored as int32 ----
    {
        const int4* mb = reinterpret_cast<const int4*>(mask + (size_t)b * LL);
        int4 a = mb[tid * 2], c = mb[tid * 2 + 1];   // 128 thr * 8 ints = 1024
        int cnt = (a.x != 0) + (a.y != 0) + (a.z != 0) + (a.w != 0)
                + (c.x != 0) + (c.y != 0) + (c.z != 0) + (c.w != 0);
        #pragma unroll
        for (int o = 16; o > 0; o >>= 1) cnt += __shfl_xor_sync(0xffffffffu, cnt, o);
        if ((tid & 31) == 0) s_red[tid >> 5] = cnt;
        __syncthreads();
        if (tid == 0)
            s_end = (s_red[0] + s_red[1] + s_red[2] + s_red[3]) - 1;
        __syncthreads();
    }
    const int endi = s_end;

    // ---- E half-column, packed f32x2: e2[k] = (E[part*32+2k][j], E[..+2k+1][j]) ----
    unsigned long long e2[16];
    #pragma unroll
    for (int k = 0; k < 16; ++k) {
        float lo = __expf(__ldg(&trans[(part * 32 + 2 * k    ) * TT + j]));
        float hi = __expf(__ldg(&trans[(part * 32 + 2 * k + 1) * TT + j]));
        PACK2(e2[k], lo, hi);
    }

    const float* lg = logits + (size_t)b * LL * TT + j;
    const float endraw = __ldg(&end_s[j]);
    const int   dst   = part ? (128 + j) : (j + ((j & 32) >> 2));
    const int   rbase = part * 40;

    // ---- init ----
    {
        float a0 = lg[0] + __ldg(&start_s[j]);
        a0 += (endi == 0) ? endraw : 0.0f;
        beta[0][dst] = __expf(a0);
    }
    __syncthreads();

    int buf = 0;
    int exoff = 0;     // exact integer sum of power-of-two normalizers

    auto step = [&](float graw, bool last) {
        const ulonglong2* bp =
            reinterpret_cast<const ulonglong2*>(&beta[buf][rbase]);
        ulonglong2 u0 = bp[0], u1 = bp[1], u2 = bp[2], u3 = bp[3];
        ulonglong2 u4 = bp[4], u5 = bp[5], u6 = bp[6], u7 = bp[7];
        const float b0 = beta[buf][0];

        // exact power-of-two renormalization: scale = 2^-ex, ex = exponent(b0)
        const int   ex    = ((__float_as_int(b0) >> 23) & 255) - 127;
        const float scale = __int_as_float((127 - ex) << 23);
        const float eg    = __expf(graw + (last ? endraw : 0.0f));
        const float m     = scale * eg;

        unsigned long long a01, a23;
        MUL2(a01, u0.x, e2[0]);        MUL2(a23, u0.y, e2[1]);
        FMA2(a01, u1.x, e2[2],  a01);  FMA2(a23, u1.y, e2[3],  a23);
        FMA2(a01, u2.x, e2[4],  a01);  FMA2(a23, u2.y, e2[5],  a23);
        FMA2(a01, u3.x, e2[6],  a01);  FMA2(a23, u3.y, e2[7],  a23);
        FMA2(a01, u4.x, e2[8],  a01);  FMA2(a23, u4.y, e2[9],  a23);
        FMA2(a01, u5.x, e2[10], a01);  FMA2(a23, u5.y, e2[11], a23);
        FMA2(a01, u6.x, e2[12], a01);  FMA2(a23, u6.y, e2[13], a23);
        FMA2(a01, u7.x, e2[14], a01);  FMA2(a23, u7.y, e2[15], a23);
        float p0, p1, p2, p3;
        UNPACK2(p0, p1, a01);
        UNPACK2(p2, p3, a23);
        float s = (p0 + p1) + (p2 + p3);
        s += __shfl_xor_sync(0xffffffffu, s, 1);   // pair (j,0)+(j,1)

        beta[buf ^ 1][dst] = s * m;
        exoff += ex;
        buf ^= 1;
        __syncthreads();
    };

    if (endi == 1023) {
        // ---- specialized full-length path: constant trip count, no breaks ----
        float g0 = lg[1 * TT], g1 = lg[2 * TT], g2 = lg[3 * TT], g3 = lg[4 * TT];
        #pragma unroll 1
        for (int t = 1; t <= 1017; t += 4) {       // covers t = 1..1020
            step(g0, false); g0 = lg[(size_t)min(t + 4, 1023) * TT];
            step(g1, false); g1 = lg[(size_t)min(t + 5, 1023) * TT];
            step(g2, false); g2 = lg[(size_t)min(t + 6, 1023) * TT];
            step(g3, false); g3 = lg[(size_t)min(t + 7, 1023) * TT];
        }
        step(g0, false);   // t = 1021
        step(g1, false);   // t = 1022
        step(g2, true);    // t = 1023, end states folded
    } else if (endi >= 1) {
        // ---- generic masked path ----
        float g0 = lg[(size_t)min(1, endi) * TT];
        float g1 = lg[(size_t)min(2, endi) * TT];
        float g2 = lg[(size_t)min(3, endi) * TT];
        float g3 = lg[(size_t)min(4, endi) * TT];
        int t = 1;
        while (t <= endi) {
            step(g0, t == endi);
            g0 = lg[(size_t)min(t + 4, endi) * TT];
            ++t; if (t > endi) break;
            step(g1, t == endi);
            g1 = lg[(size_t)min(t + 4, endi) * TT];
            ++t; if (t > endi) break;
            step(g2, t == endi);
            g2 = lg[(size_t)min(t + 4, endi) * TT];
            ++t; if (t > endi) break;
            step(g3, t == endi);
            g3 = lg[(size_t)min(t + 4, endi) * TT];
            ++t;
        }
    }

    // ---- final: out[b] = exoff*ln2 + log(sum_j beta[j]) ----
    {
        const float4* fv = reinterpret_cast<const float4*>(&beta[buf][rbase]);
        float ls = 0.0f;
        #pragma unroll
        for (int q = 0; q < 8; ++q) {
            float4 x = fv[q];
            ls += (x.x + x.y) + (x.z + x.w);
        }
        ls += __shfl_xor_sync(0xffffffffu, ls, 1);
        if (tid == 0)
            out[b] = __int2float_rn(exoff) * 0.693147180559945f + __logf(ls);
    }
}

extern "C" void kernel_launch(void* const* d_in, const int* in_sizes, int n_in,
                              void* d_out, int out_size) {
    const float* logits        = (const float*)d_in[0];
    const float* transitions   = (const float*)d_in[1];
    const float* start_states  = (const float*)d_in[2];
    const float* end_states    = (const float*)d_in[3];
    const int*   mask          = (const int*)d_in[4];
    float* out = (float*)d_out;
    (void)in_sizes; (void)n_in; (void)out_size;

    crf_forward_kernel<<<NB, 128>>>(logits, transitions, start_states,
                                    end_states, mask, out);
}

// round 5
// speedup vs baseline: 5.1875x; 1.7701x over previous
#include <cuda_runtime.h>

#define NB 32
#define LL 1024
#define TT 64

#define FMA2(d,a,b,c) asm("fma.rn.f32x2 %0, %1, %2, %3;" : "=l"(d) : "l"(a), "l"(b), "l"(c))
#define MUL2(d,a,b)   asm("mul.rn.f32x2 %0, %1, %2;"     : "=l"(d) : "l"(a), "l"(b))
#define UNPACK2(lo,hi,v) asm("mov.b64 {%0,%1}, %2;" : "=f"(lo), "=f"(hi) : "l"(v))
#define PACK2(v,lo,hi)   asm("mov.b64 %0, {%1,%2};" : "=l"(v) : "f"(lo), "f"(hi))

// cross-kernel scratch (device globals: the sanctioned no-alloc scratch)
__device__ float g_A[NB][TT];    // forward vector A_mid
__device__ float g_R[NB][TT];    // backward vector R_mid
__device__ int   g_exF[NB];
__device__ int   g_exB[NB];

__global__ __launch_bounds__(128, 1)
void crf_half_kernel(const float* __restrict__ logits,     // [B,L,T]
                     const float* __restrict__ trans,      // [T,T]
                     const float* __restrict__ start_s,    // [T]
                     const float* __restrict__ end_s,      // [T]
                     const int* __restrict__ mask)         // [B,L] bool as int32
{
    const int b    = blockIdx.x;
    const int dir  = blockIdx.y;          // 0 = forward, 1 = backward
    const int tid  = threadIdx.x;
    const int j    = tid >> 1;            // output state 0..63
    const int part = tid & 1;             // input-half 0..1

    // live vector at padded slots [0..31]∪[40..71] (bank-conflict-free);
    // [128..191] duplicate-write scratch for part==1 (branchless stores)
    __shared__ __align__(16) float beta[2][192];
    __shared__ int s_red[4];
    __shared__ int s_end;

    // ---- end_idx = count(mask != 0) - 1 ; mask stored as int32 ----
    {
        const int4* mb = reinterpret_cast<const int4*>(mask + (size_t)b * LL);
        int4 a = mb[tid * 2], c = mb[tid * 2 + 1];
        int cnt = (a.x != 0) + (a.y != 0) + (a.z != 0) + (a.w != 0)
                + (c.x != 0) + (c.y != 0) + (c.z != 0) + (c.w != 0);
        #pragma unroll
        for (int o = 16; o > 0; o >>= 1) cnt += __shfl_xor_sync(0xffffffffu, cnt, o);
        if ((tid & 31) == 0) s_red[tid >> 5] = cnt;
        __syncthreads();
        if (tid == 0)
            s_end = (s_red[0] + s_red[1] + s_red[2] + s_red[3]) - 1;
        __syncthreads();
    }
    const int endi = s_end;
    const int mid  = (endi <= 1) ? 0 : min((endi + 1) >> 1, endi - 1);

    // ---- E slice, packed f32x2.
    // forward: columns  e2[k] = (E[part*32+2k][j], E[part*32+2k+1][j])
    // backward: rows    e2[k] = (E[j][part*32+2k], E[j][part*32+2k+1])
    unsigned long long e2[16];
    #pragma unroll
    for (int k = 0; k < 16; ++k) {
        int i0 = dir ? (j * TT + part * 32 + 2 * k)
                     : ((part * 32 + 2 * k) * TT + j);
        int i1 = dir ? (j * TT + part * 32 + 2 * k + 1)
                     : ((part * 32 + 2 * k + 1) * TT + j);
        float lo = __expf(__ldg(&trans[i0]));
        float hi = __expf(__ldg(&trans[i1]));
        PACK2(e2[k], lo, hi);
    }

    const float* lg = logits + (size_t)b * LL * TT + j;
    const int dst   = part ? (128 + j) : (j + ((j & 32) >> 2));
    const int rbase = part * 40;
    const int rd    = j + ((j & 32) >> 2);      // padded read slot for state j

    int buf = 0;
    int exoff = 0;

    // one recursion step: read beta[buf], dot with e2, scale by 2^-ex * eg, store
    auto step = [&](float graw) {
        const ulonglong2* bp =
            reinterpret_cast<const ulonglong2*>(&beta[buf][rbase]);
        ulonglong2 u0 = bp[0], u1 = bp[1], u2 = bp[2], u3 = bp[3];
        ulonglong2 u4 = bp[4], u5 = bp[5], u6 = bp[6], u7 = bp[7];
        const float b0 = beta[buf][0];

        const int   ex    = ((__float_as_int(b0) >> 23) & 255) - 127;
        const float scale = __int_as_float((127 - ex) << 23);
        const float m     = scale * __expf(graw);

        unsigned long long a01, a23;
        MUL2(a01, u0.x, e2[0]);        MUL2(a23, u0.y, e2[1]);
        FMA2(a01, u1.x, e2[2],  a01);  FMA2(a23, u1.y, e2[3],  a23);
        FMA2(a01, u2.x, e2[4],  a01);  FMA2(a23, u2.y, e2[5],  a23);
        FMA2(a01, u3.x, e2[6],  a01);  FMA2(a23, u3.y, e2[7],  a23);
        FMA2(a01, u4.x, e2[8],  a01);  FMA2(a23, u4.y, e2[9],  a23);
        FMA2(a01, u5.x, e2[10], a01);  FMA2(a23, u5.y, e2[11], a23);
        FMA2(a01, u6.x, e2[12], a01);  FMA2(a23, u6.y, e2[13], a23);
        FMA2(a01, u7.x, e2[14], a01);  FMA2(a23, u7.y, e2[15], a23);
        float p0, p1, p2, p3;
        UNPACK2(p0, p1, a01);
        UNPACK2(p2, p3, a23);
        float s = (p0 + p1) + (p2 + p3);
        s += __shfl_xor_sync(0xffffffffu, s, 1);

        beta[buf ^ 1][dst] = s * m;
        exoff += ex;
        buf ^= 1;
        __syncthreads();
    };

    if (dir == 0) {
        // ================= FORWARD: A_mid, steps t = 1..mid =================
        {
            float a0 = lg[0] + __ldg(&start_s[j]);
            a0 += (endi == 0) ? __ldg(&end_s[j]) : 0.0f;   // endi==0 edge
            beta[0][dst] = __expf(a0);
        }
        __syncthreads();

        if (endi == 1023) {
            // mid = 512: exactly 512 steps, no clamps (prefetch max idx 516)
            float g0 = lg[1 * TT], g1 = lg[2 * TT], g2 = lg[3 * TT], g3 = lg[4 * TT];
            #pragma unroll 1
            for (int t = 1; t <= 509; t += 4) {
                step(g0); g0 = lg[(size_t)(t + 4) * TT];
                step(g1); g1 = lg[(size_t)(t + 5) * TT];
                step(g2); g2 = lg[(size_t)(t + 6) * TT];
                step(g3); g3 = lg[(size_t)(t + 7) * TT];
            }
        } else {
            int t = 1;
            float gn = (t <= mid) ? lg[(size_t)t * TT] : 0.0f;
            #pragma unroll 1
            while (t <= mid) {
                float gc = gn;
                gn = (t + 1 <= mid) ? lg[(size_t)(t + 1) * TT] : 0.0f;
                step(gc);
                ++t;
            }
        }

        if (part == 0) g_A[b][j] = beta[buf][rd];
        if (tid == 0)  g_exF[b] = exoff;
    } else {
        // ============ BACKWARD: y_t = eg_t ∘ (E y_{t+1}), then R_mid ============
        if (endi == 0) {
            if (part == 0) g_R[b][j] = 1.0f;
            if (tid == 0)  g_exB[b] = 0;
            return;
        }
        // init y_endi = exp(logits[endi] + end)
        beta[0][dst] = __expf(lg[(size_t)endi * TT] + __ldg(&end_s[j]));
        __syncthreads();

        if (endi == 1023) {
            // iterate t = 1022 .. 513 (510 steps), then epilogue
            float g0 = lg[1022 * TT], g1 = lg[1021 * TT],
                  g2 = lg[1020 * TT], g3 = lg[1019 * TT];
            #pragma unroll 1
            for (int t = 1022; t >= 518; t -= 4) {
                step(g0); g0 = lg[(size_t)(t - 4) * TT];
                step(g1); g1 = lg[(size_t)(t - 5) * TT];
                step(g2); g2 = lg[(size_t)(t - 6) * TT];
                step(g3); g3 = lg[(size_t)(t - 7) * TT];
            }
            step(g0);   // t = 514
            step(g1);   // t = 513
        } else {
            int t = endi - 1;
            float gn = (t >= mid + 1) ? lg[(size_t)t * TT] : 0.0f;
            #pragma unroll 1
            while (t >= mid + 1) {
                float gc = gn;
                gn = (t - 1 >= mid + 1) ? lg[(size_t)(t - 1) * TT] : 0.0f;
                step(gc);
                --t;
            }
        }

        // epilogue matvec (no eg): R_mid = 2^-ex * (E y_{mid+1})
        {
            const ulonglong2* bp =
                reinterpret_cast<const ulonglong2*>(&beta[buf][rbase]);
            ulonglong2 u0 = bp[0], u1 = bp[1], u2 = bp[2], u3 = bp[3];
            ulonglong2 u4 = bp[4], u5 = bp[5], u6 = bp[6], u7 = bp[7];
            const float b0 = beta[buf][0];
            const int   ex    = ((__float_as_int(b0) >> 23) & 255) - 127;
            const float scale = __int_as_float((127 - ex) << 23);

            unsigned long long a01, a23;
            MUL2(a01, u0.x, e2[0]);        MUL2(a23, u0.y, e2[1]);
            FMA2(a01, u1.x, e2[2],  a01);  FMA2(a23, u1.y, e2[3],  a23);
            FMA2(a01, u2.x, e2[4],  a01);  FMA2(a23, u2.y, e2[5],  a23);
            FMA2(a01, u3.x, e2[6],  a01);  FMA2(a23, u3.y, e2[7],  a23);
            FMA2(a01, u4.x, e2[8],  a01);  FMA2(a23, u4.y, e2[9],  a23);
            FMA2(a01, u5.x, e2[10], a01);  FMA2(a23, u5.y, e2[11], a23);
            FMA2(a01, u6.x, e2[12], a01);  FMA2(a23, u6.y, e2[13], a23);
            FMA2(a01, u7.x, e2[14], a01);  FMA2(a23, u7.y, e2[15], a23);
            float p0, p1, p2, p3;
            UNPACK2(p0, p1, a01);
            UNPACK2(p2, p3, a23);
            float s = (p0 + p1) + (p2 + p3);
            s += __shfl_xor_sync(0xffffffffu, s, 1);

            if (part == 0) g_R[b][j] = s * scale;
            if (tid == 0)  g_exB[b] = exoff + ex;
        }
    }
}

// out[b] = log( A_mid · R_mid ) + (exF + exB) * ln2
__global__ void crf_combine_kernel(float* __restrict__ out)
{
    const int b = threadIdx.y;   // batch
    const int l = threadIdx.x;   // lane
    float s = g_A[b][l] * g_R[b][l] + g_A[b][l + 32] * g_R[b][l + 32];
    #pragma unroll
    for (int o = 16; o > 0; o >>= 1) s += __shfl_xor_sync(0xffffffffu, s, o);
    if (l == 0)
        out[b] = __logf(s) +
                 __int2float_rn(g_exF[b] + g_exB[b]) * 0.693147180559945f;
}

extern "C" void kernel_launch(void* const* d_in, const int* in_sizes, int n_in,
                              void* d_out, int out_size) {
    const float* logits        = (const float*)d_in[0];
    const float* transitions   = (const float*)d_in[1];
    const float* start_states  = (const float*)d_in[2];
    const float* end_states    = (const float*)d_in[3];
    const int*   mask          = (const int*)d_in[4];
    float* out = (float*)d_out;
    (void)in_sizes; (void)n_in; (void)out_size;

    dim3 grid(NB, 2);
    crf_half_kernel<<<grid, 128>>>(logits, transitions, start_states,
                                   end_states, mask);
    crf_combine_kernel<<<1, dim3(32, NB)>>>(out);
}

// round 6
// speedup vs baseline: 7.3019x; 1.4076x over previous
#include <cuda_runtime.h>

#define NB  32
#define LL  1024
#define TT  64
#define KSEG 12
#define NCH (2 * KSEG - 2)     // 22 chains per batch

#define FMA2(d,a,b,c) asm("fma.rn.f32x2 %0, %1, %2, %3;" : "=l"(d) : "l"(a), "l"(b), "l"(c))
#define MUL2(d,a,b)   asm("mul.rn.f32x2 %0, %1, %2;"     : "=l"(d) : "l"(a), "l"(b))
#define UNPACK2(lo,hi,v) asm("mov.b64 {%0,%1}, %2;" : "=f"(lo), "=f"(hi) : "l"(v))
#define PACK2(v,lo,hi)   asm("mov.b64 %0, {%1,%2};" : "=l"(v) : "f"(lo), "f"(hi))

// segment cut points: c[k] = (k*1023)/12
__device__ __constant__ int d_cut[KSEG + 1] =
    {0, 85, 170, 255, 341, 426, 511, 597, 682, 767, 853, 938, 1023};

// cross-kernel scratch (device globals: the sanctioned no-alloc scratch)
__device__ float g_vec[NB][NCH][TT];   // normalized chain output vectors
__device__ int   g_ex[NB][NCH];        // integer pow2 exponent offsets
__device__ float g_gen[NB];            // generic-path result
__device__ int   g_isgen[NB];

__global__ __launch_bounds__(128, 1)
void crf_seg_kernel(const float* __restrict__ logits,     // [B,L,T]
                    const float* __restrict__ trans,      // [T,T]
                    const float* __restrict__ start_s,    // [T]
                    const float* __restrict__ end_s,      // [T]
                    const int* __restrict__ mask)         // [B,L] bool as int32
{
    const int b    = blockIdx.x;
    const int cid  = blockIdx.y;          // chain id 0..NCH-1
    const int tid  = threadIdx.x;
    const int j    = tid >> 1;            // output state 0..63
    const int part = tid & 1;             // input-half 0..1

    // live vector at padded slots [0..31]∪[40..71] (bank-conflict-free);
    // [128..191] duplicate-write scratch for part==1 (branchless stores)
    __shared__ __align__(16) float beta[2][192];
    __shared__ int s_red[4];
    __shared__ int s_end;

    // ---- end_idx = count(mask != 0) - 1 ; mask stored as int32 ----
    {
        const int4* mb = reinterpret_cast<const int4*>(mask + (size_t)b * LL);
        int4 a = mb[tid * 2], c = mb[tid * 2 + 1];
        int cnt = (a.x != 0) + (a.y != 0) + (a.z != 0) + (a.w != 0)
                + (c.x != 0) + (c.y != 0) + (c.z != 0) + (c.w != 0);
        #pragma unroll
        for (int o = 16; o > 0; o >>= 1) cnt += __shfl_xor_sync(0xffffffffu, cnt, o);
        if ((tid & 31) == 0) s_red[tid >> 5] = cnt;
        __syncthreads();
        if (tid == 0)
            s_end = (s_red[0] + s_red[1] + s_red[2] + s_red[3]) - 1;
        __syncthreads();
    }
    const int endi = s_end;
    const bool generic = (endi != 1023);
    if (generic && cid != 0) return;

    // chain type:
    //   cid 0      : R   forward from a0, steps 1..c[1]
    //   cid 1..10  : Q_k (k=cid+1) forward from ones, steps c[k-1]+1..c[k]
    //   cid 11..20 : P_k (k=cid-9) backward u-recursion + epilogue p = E u
    //   cid 21     : W   backward from eg_1023 (incl end), epilogue w = E u
    const bool bwd = (!generic) && (cid >= 11);

    // ---- E slice, packed f32x2. fwd: columns of E; bwd: rows of E ----
    unsigned long long e2[16];
    #pragma unroll
    for (int k = 0; k < 16; ++k) {
        int i0 = bwd ? (j * TT + part * 32 + 2 * k)
                     : ((part * 32 + 2 * k) * TT + j);
        int i1 = bwd ? (j * TT + part * 32 + 2 * k + 1)
                     : ((part * 32 + 2 * k + 1) * TT + j);
        float lo = __expf(__ldg(&trans[i0]));
        float hi = __expf(__ldg(&trans[i1]));
        PACK2(e2[k], lo, hi);
    }

    const float* lg = logits + (size_t)b * LL * TT + j;
    const float endraw = __ldg(&end_s[j]);
    const int dst   = part ? (128 + j) : (j + ((j & 32) >> 2));
    const int rbase = part * 40;
    const int rd    = j + ((j & 32) >> 2);

    int buf = 0;
    int exoff = 0;

    // one recursion step: read beta[buf], dot with e2, scale by 2^-ex * eg, store
    auto step = [&](float graw) {
        const ulonglong2* bp =
            reinterpret_cast<const ulonglong2*>(&beta[buf][rbase]);
        ulonglong2 u0 = bp[0], u1 = bp[1], u2 = bp[2], u3 = bp[3];
        ulonglong2 u4 = bp[4], u5 = bp[5], u6 = bp[6], u7 = bp[7];
        const float b0 = beta[buf][0];

        const int   ex    = ((__float_as_int(b0) >> 23) & 255) - 127;
        const float scale = __int_as_float((127 - ex) << 23);
        const float m     = scale * __expf(graw);

        unsigned long long a01, a23;
        MUL2(a01, u0.x, e2[0]);        MUL2(a23, u0.y, e2[1]);
        FMA2(a01, u1.x, e2[2],  a01);  FMA2(a23, u1.y, e2[3],  a23);
        FMA2(a01, u2.x, e2[4],  a01);  FMA2(a23, u2.y, e2[5],  a23);
        FMA2(a01, u3.x, e2[6],  a01);  FMA2(a23, u3.y, e2[7],  a23);
        FMA2(a01, u4.x, e2[8],  a01);  FMA2(a23, u4.y, e2[9],  a23);
        FMA2(a01, u5.x, e2[10], a01);  FMA2(a23, u5.y, e2[11], a23);
        FMA2(a01, u6.x, e2[12], a01);  FMA2(a23, u6.y, e2[13], a23);
        FMA2(a01, u7.x, e2[14], a01);  FMA2(a23, u7.y, e2[15], a23);
        float p0, p1, p2, p3;
        UNPACK2(p0, p1, a01);
        UNPACK2(p2, p3, a23);
        float s = (p0 + p1) + (p2 + p3);
        s += __shfl_xor_sync(0xffffffffu, s, 1);

        beta[buf ^ 1][dst] = s * m;
        exoff += ex;
        buf ^= 1;
        __syncthreads();
    };

    if (generic) {
        // ======== correct fallback for masked inputs: full forward ========
        {
            float a0 = lg[0] + __ldg(&start_s[j]);
            a0 += (endi == 0) ? endraw : 0.0f;
            beta[0][dst] = __expf(a0);
        }
        __syncthreads();
        #pragma unroll 1
        for (int t = 1; t <= endi; ++t)
            step(lg[(size_t)t * TT] + ((t == endi) ? endraw : 0.0f));
        const float4* fv = reinterpret_cast<const float4*>(&beta[buf][rbase]);
        float ls = 0.0f;
        #pragma unroll
        for (int q = 0; q < 8; ++q) {
            float4 x = fv[q];
            ls += (x.x + x.y) + (x.z + x.w);
        }
        ls += __shfl_xor_sync(0xffffffffu, ls, 1);
        if (tid == 0) {
            g_gen[b] = __int2float_rn(exoff) * 0.693147180559945f + __logf(ls);
            g_isgen[b] = 1;
        }
        return;
    }
    if (cid == 0 && tid == 0) g_isgen[b] = 0;

    if (!bwd) {
        // ================= forward chains (R, Q_k) =================
        int lo, hi;
        if (cid == 0) {
            lo = 1; hi = d_cut[1];
            float a0 = lg[0] + __ldg(&start_s[j]);
            beta[0][dst] = __expf(a0);
        } else {
            int k = cid + 1;
            lo = d_cut[k - 1] + 1; hi = d_cut[k];
            beta[0][dst] = 1.0f;
        }
        __syncthreads();

        // ascending, distance-2 prefetch (reads ≤ hi+2 ≤ 940: in bounds)
        float gA = lg[(size_t)lo * TT];
        float gB = lg[(size_t)(lo + 1) * TT];
        int t = lo;
        #pragma unroll 1
        for (; t + 1 <= hi; t += 2) {
            step(gA); gA = lg[(size_t)(t + 2) * TT];
            step(gB); gB = lg[(size_t)(t + 3) * TT];
        }
        if (t <= hi) step(gA);

        if (part == 0) g_vec[b][cid][j] = beta[buf][rd];
        if (tid == 0)  g_ex[b][cid] = exoff;
    } else {
        // ============ backward chains (P_k, W): u-recursion + epilogue ============
        int lo0, hi0;
        if (cid == NCH - 1) {           // W
            lo0 = d_cut[KSEG - 1] + 1;  // 939
            hi0 = 1022;
            beta[0][dst] = __expf(lg[(size_t)1023 * TT] + endraw);
        } else {                        // P_k
            int k = cid - 9;
            lo0 = d_cut[k - 1] + 1;
            hi0 = d_cut[k] - 1;
            beta[0][dst] = __expf(lg[(size_t)d_cut[k] * TT]);
        }
        __syncthreads();

        // descending, distance-2 prefetch (reads ≥ lo0-2 ≥ 84: in bounds)
        float gA = lg[(size_t)hi0 * TT];
        float gB = lg[(size_t)(hi0 - 1) * TT];
        int t = hi0;
        #pragma unroll 1
        for (; t - 1 >= lo0; t -= 2) {
            step(gA); gA = lg[(size_t)(t - 2) * TT];
            step(gB); gB = lg[(size_t)(t - 3) * TT];
        }
        if (t >= lo0) step(gA);

        // epilogue matvec (no eg): p = 2^-ex * (E u_lo0)
        {
            const ulonglong2* bp =
                reinterpret_cast<const ulonglong2*>(&beta[buf][rbase]);
            ulonglong2 u0 = bp[0], u1 = bp[1], u2 = bp[2], u3 = bp[3];
            ulonglong2 u4 = bp[4], u5 = bp[5], u6 = bp[6], u7 = bp[7];
            const float b0 = beta[buf][0];
            const int   ex    = ((__float_as_int(b0) >> 23) & 255) - 127;
            const float scale = __int_as_float((127 - ex) << 23);

            unsigned long long a01, a23;
            MUL2(a01, u0.x, e2[0]);        MUL2(a23, u0.y, e2[1]);
            FMA2(a01, u1.x, e2[2],  a01);  FMA2(a23, u1.y, e2[3],  a23);
            FMA2(a01, u2.x, e2[4],  a01);  FMA2(a23, u2.y, e2[5],  a23);
            FMA2(a01, u3.x, e2[6],  a01);  FMA2(a23, u3.y, e2[7],  a23);
            FMA2(a01, u4.x, e2[8],  a01);  FMA2(a23, u4.y, e2[9],  a23);
            FMA2(a01, u5.x, e2[10], a01);  FMA2(a23, u5.y, e2[11], a23);
            FMA2(a01, u6.x, e2[12], a01);  FMA2(a23, u6.y, e2[13], a23);
            FMA2(a01, u7.x, e2[14], a01);  FMA2(a23, u7.y, e2[15], a23);
            float p0, p1, p2, p3;
            UNPACK2(p0, p1, a01);
            UNPACK2(p2, p3, a23);
            float s = (p0 + p1) + (p2 + p3);
            s += __shfl_xor_sync(0xffffffffu, s, 1);

            if (part == 0) g_vec[b][cid][j] = s * scale;
            if (tid == 0)  g_ex[b][cid] = exoff + ex;
        }
    }
}

// telescoped rank-1 combine:
// logZ = sum_{k=2}^{K-1} [log(p_k . x_{k-1}) - log(sum q_k)] + log(w . q_{K-1})
//        + ln2 * (exR + exW + sum exP_k)
// where x_1 = r (cid 0), x_{k-1} = q_{k-1} (cid k-2), p_k = cid k+9, w = cid 21
__global__ void crf_combine_kernel(float* __restrict__ out)
{
    const int l = threadIdx.x;   // lane
    const int b = threadIdx.y;   // batch
    if (g_isgen[b]) { if (l == 0) out[b] = g_gen[b]; return; }

    float va[NCH], vb[NCH];
    #pragma unroll
    for (int c = 0; c < NCH; ++c) {
        va[c] = g_vec[b][c][l];
        vb[c] = g_vec[b][c][l + 32];
    }

    float acc = 0.0f;
    #pragma unroll
    for (int k = 2; k <= KSEG - 1; ++k) {
        float d = va[k + 9] * va[k - 2] + vb[k + 9] * vb[k - 2];
        float s = va[k - 1] + vb[k - 1];
        #pragma unroll
        for (int o = 16; o > 0; o >>= 1) {
            d += __shfl_xor_sync(0xffffffffu, d, o);
            s += __shfl_xor_sync(0xffffffffu, s, o);
        }
        acc += __logf(d) - __logf(s);
    }
    {
        float d = va[NCH - 1] * va[KSEG - 2] + vb[NCH - 1] * vb[KSEG - 2];
        #pragma unroll
        for (int o = 16; o > 0; o >>= 1) d += __shfl_xor_sync(0xffffffffu, d, o);
        acc += __logf(d);
    }

    if (l == 0) {
        int ex = g_ex[b][0] + g_ex[b][NCH - 1];
        #pragma unroll
        for (int c = 11; c <= 20; ++c) ex += g_ex[b][c];
        out[b] = acc + __int2float_rn(ex) * 0.693147180559945f;
    }
}

extern "C" void kernel_launch(void* const* d_in, const int* in_sizes, int n_in,
                              void* d_out, int out_size) {
    const float* logits        = (const float*)d_in[0];
    const float* transitions   = (const float*)d_in[1];
    const float* start_states  = (const float*)d_in[2];
    const float* end_states    = (const float*)d_in[3];
    const int*   mask          = (const int*)d_in[4];
    float* out = (float*)d_out;
    (void)in_sizes; (void)n_in; (void)out_size;

    dim3 grid(NB, NCH);
    crf_seg_kernel<<<grid, 128>>>(logits, transitions, start_states,
                                  end_states, mask);
    crf_combine_kernel<<<1, dim3(32, NB)>>>(out);
}

// round 8
// speedup vs baseline: 7.3433x; 1.0057x over previous
#include <cuda_runtime.h>

#define NB  32
#define LL  1024
#define TT  64
#define KSEG 12
#define NCH (2 * KSEG - 2)     // 22 chains per batch

#define FMA2(d,a,b,c) asm("fma.rn.f32x2 %0, %1, %2, %3;" : "=l"(d) : "l"(a), "l"(b), "l"(c))
#define MUL2(d,a,b)   asm("mul.rn.f32x2 %0, %1, %2;"     : "=l"(d) : "l"(a), "l"(b))
#define UNPACK2(lo,hi,v) asm("mov.b64 {%0,%1}, %2;" : "=f"(lo), "=f"(hi) : "l"(v))
#define PACK2(v,lo,hi)   asm("mov.b64 %0, {%1,%2};" : "=l"(v) : "f"(lo), "f"(hi))

// segment cut points: c[k] = (k*1023)/12
__device__ __constant__ int d_cut[KSEG + 1] =
    {0, 85, 170, 255, 341, 426, 511, 597, 682, 767, 853, 938, 1023};

// device-global scratch (sanctioned no-alloc scratch)
__device__ float g_P[NB * LL * TT];    // exp(logits), precomputed
__device__ float g_vec[NB][NCH][TT];   // normalized chain output vectors
__device__ int   g_ex[NB][NCH];        // integer pow2 exponent offsets
__device__ float g_gen[NB];            // generic-path result
__device__ int   g_isgen[NB];

// ---------------- pre-exponentiation: g_P = exp(logits) ----------------
__global__ __launch_bounds__(256)
void crf_exp_kernel(const float* __restrict__ logits)
{
    int i = blockIdx.x * 256 + threadIdx.x;          // float4 index
    const float4* in = reinterpret_cast<const float4*>(logits);
    float4* outp = reinterpret_cast<float4*>(g_P);
    float4 v = in[i];
    v.x = __expf(v.x); v.y = __expf(v.y);
    v.z = __expf(v.z); v.w = __expf(v.w);
    outp[i] = v;
}

__global__ __launch_bounds__(128, 1)
void crf_seg_kernel(const float* __restrict__ logits,     // [B,L,T]
                    const float* __restrict__ trans,      // [T,T]
                    const float* __restrict__ start_s,    // [T]
                    const float* __restrict__ end_s,      // [T]
                    const int* __restrict__ mask)         // [B,L] bool as int32
{
    const int b    = blockIdx.x;
    const int cid  = blockIdx.y;          // chain id 0..NCH-1
    const int tid  = threadIdx.x;
    const int j    = tid >> 1;            // output state 0..63
    const int part = tid & 1;             // input-half 0..1

    // live vector at padded slots [0..31]∪[40..71] (bank-conflict-free);
    // [128..191] duplicate-write scratch for part==1 (branchless stores)
    __shared__ __align__(16) float beta[2][192];
    __shared__ int s_red[4];
    __shared__ int s_end;

    // ---- end_idx = count(mask != 0) - 1 ; mask stored as int32 ----
    {
        const int4* mb = reinterpret_cast<const int4*>(mask + (size_t)b * LL);
        int4 a = mb[tid * 2], c = mb[tid * 2 + 1];
        int cnt = (a.x != 0) + (a.y != 0) + (a.z != 0) + (a.w != 0)
                + (c.x != 0) + (c.y != 0) + (c.z != 0) + (c.w != 0);
        #pragma unroll
        for (int o = 16; o > 0; o >>= 1) cnt += __shfl_xor_sync(0xffffffffu, cnt, o);
        if ((tid & 31) == 0) s_red[tid >> 5] = cnt;
        __syncthreads();
        if (tid == 0)
            s_end = (s_red[0] + s_red[1] + s_red[2] + s_red[3]) - 1;
        __syncthreads();
    }
    const int endi = s_end;
    const bool generic = (endi != 1023);
    if (generic && cid != 0) return;

    const bool bwd = (!generic) && (cid >= 11);
    // fast path: E' = exp(trans) * 2^-7 (constant renorm, exact pow2)
    const float esc = generic ? 1.0f : 0.0078125f;

    // ---- E slice, packed f32x2. fwd: columns of E; bwd: rows of E ----
    unsigned long long e2[16];
    #pragma unroll
    for (int k = 0; k < 16; ++k) {
        int i0 = bwd ? (j * TT + part * 32 + 2 * k)
                     : ((part * 32 + 2 * k) * TT + j);
        int i1 = bwd ? (j * TT + part * 32 + 2 * k + 1)
                     : ((part * 32 + 2 * k + 1) * TT + j);
        float lo = __expf(__ldg(&trans[i0])) * esc;
        float hi = __expf(__ldg(&trans[i1])) * esc;
        PACK2(e2[k], lo, hi);
    }

    const float* lg = logits + (size_t)b * LL * TT + j;
    const float* Pp = g_P    + (size_t)b * LL * TT + j;
    const float endraw = __ldg(&end_s[j]);
    const int dst   = part ? (128 + j) : (j + ((j & 32) >> 2));
    const int rbase = part * 40;
    const int rd    = j + ((j & 32) >> 2);

    int buf = 0;

    // shared dot: returns Σ_i beta[buf][i] * e2col(i)
    auto dot = [&]() -> float {
        const ulonglong2* bp =
            reinterpret_cast<const ulonglong2*>(&beta[buf][rbase]);
        ulonglong2 u0 = bp[0], u1 = bp[1], u2 = bp[2], u3 = bp[3];
        ulonglong2 u4 = bp[4], u5 = bp[5], u6 = bp[6], u7 = bp[7];
        unsigned long long a01, a23;
        MUL2(a01, u0.x, e2[0]);        MUL2(a23, u0.y, e2[1]);
        FMA2(a01, u1.x, e2[2],  a01);  FMA2(a23, u1.y, e2[3],  a23);
        FMA2(a01, u2.x, e2[4],  a01);  FMA2(a23, u2.y, e2[5],  a23);
        FMA2(a01, u3.x, e2[6],  a01);  FMA2(a23, u3.y, e2[7],  a23);
        FMA2(a01, u4.x, e2[8],  a01);  FMA2(a23, u4.y, e2[9],  a23);
        FMA2(a01, u5.x, e2[10], a01);  FMA2(a23, u5.y, e2[11], a23);
        FMA2(a01, u6.x, e2[12], a01);  FMA2(a23, u6.y, e2[13], a23);
        FMA2(a01, u7.x, e2[14], a01);  FMA2(a23, u7.y, e2[15], a23);
        float p0, p1, p2, p3;
        UNPACK2(p0, p1, a01);
        UNPACK2(p2, p3, a23);
        float s = (p0 + p1) + (p2 + p3);
        s += __shfl_xor_sync(0xffffffffu, s, 1);
        return s;
    };

    // fast step: no renorm, pg already exponentiated
    auto step_fast = [&](float pg) {
        float s = dot();
        beta[buf ^ 1][dst] = s * pg;
        buf ^= 1;
        __syncthreads();
    };

    // write-out: normalize by pow2 exponent of beta[0], record ex + 7*S
    auto writeout = [&](int S) {
        const float b0 = beta[buf][0];
        const int   ex    = ((__float_as_int(b0) >> 23) & 255) - 127;
        const float scale = __int_as_float((127 - ex) << 23);
        if (part == 0) g_vec[b][cid][j] = beta[buf][rd] * scale;
        if (tid == 0)  g_ex[b][cid] = ex + 7 * S;
    };

    if (generic) {
        // ======== correct fallback for masked inputs: full forward with
        //          per-step pow2 renorm (esc==1, so E unscaled) ========
        int exoff = 0;
        {
            float a0 = lg[0] + __ldg(&start_s[j]);
            a0 += (endi == 0) ? endraw : 0.0f;
            beta[0][dst] = __expf(a0);
        }
        __syncthreads();
        #pragma unroll 1
        for (int t = 1; t <= endi; ++t) {
            const float b0 = beta[buf][0];
            const int   ex    = ((__float_as_int(b0) >> 23) & 255) - 127;
            const float scale = __int_as_float((127 - ex) << 23);
            const float m     = scale *
                __expf(lg[(size_t)t * TT] + ((t == endi) ? endraw : 0.0f));
            float s = dot();
            beta[buf ^ 1][dst] = s * m;
            exoff += ex;
            buf ^= 1;
            __syncthreads();
        }
        const float4* fv = reinterpret_cast<const float4*>(&beta[buf][rbase]);
        float ls = 0.0f;
        #pragma unroll
        for (int q = 0; q < 8; ++q) {
            float4 x = fv[q];
            ls += (x.x + x.y) + (x.z + x.w);
        }
        ls += __shfl_xor_sync(0xffffffffu, ls, 1);
        if (tid == 0) {
            g_gen[b] = __int2float_rn(exoff) * 0.693147180559945f + __logf(ls);
            g_isgen[b] = 1;
        }
        return;
    }
    if (cid == 0 && tid == 0) g_isgen[b] = 0;

    if (!bwd) {
        // ================= forward chains (R, Q_k) =================
        int lo, hi;
        if (cid == 0) {
            lo = 1; hi = d_cut[1];
            beta[0][dst] = Pp[0] * __expf(__ldg(&start_s[j]));
        } else {
            int k = cid + 1;
            lo = d_cut[k - 1] + 1; hi = d_cut[k];
            beta[0][dst] = 1.0f;
        }
        __syncthreads();

        float gA = Pp[(size_t)lo * TT];
        float gB = Pp[(size_t)(lo + 1) * TT];
        int t = lo;
        #pragma unroll 1
        for (; t + 1 <= hi; t += 2) {
            step_fast(gA); gA = Pp[(size_t)(t + 2) * TT];
            step_fast(gB); gB = Pp[(size_t)(t + 3) * TT];
        }
        if (t <= hi) step_fast(gA);

        writeout(hi - lo + 1);
    } else {
        // ============ backward chains (P_k, W): u-recursion + epilogue ============
        int lo0, hi0;
        if (cid == NCH - 1) {           // W
            lo0 = d_cut[KSEG - 1] + 1;  // 939
            hi0 = 1022;
            beta[0][dst] = Pp[(size_t)1023 * TT] * __expf(endraw);
        } else {                        // P_k
            int k = cid - 9;
            lo0 = d_cut[k - 1] + 1;
            hi0 = d_cut[k] - 1;
            beta[0][dst] = Pp[(size_t)d_cut[k] * TT];
        }
        __syncthreads();

        float gA = Pp[(size_t)hi0 * TT];
        float gB = Pp[(size_t)(hi0 - 1) * TT];
        int t = hi0;
        #pragma unroll 1
        for (; t - 1 >= lo0; t -= 2) {
            step_fast(gA); gA = Pp[(size_t)(t - 2) * TT];
            step_fast(gB); gB = Pp[(size_t)(t - 3) * TT];
        }
        if (t >= lo0) step_fast(gA);

        step_fast(1.0f);                // epilogue matvec p = E' u
        writeout((hi0 - lo0 + 1) + 1);
    }
}

// telescoped rank-1 combine, one block per batch:
// logZ = sum_{k=2}^{K-1} [log(p_k . x_{k-1}) - log(sum q_k)] + log(w . q_{K-1})
//        + ln2 * (exR + exW + sum exP_k)     (q scales cancel exactly)
__global__ void crf_combine_kernel(float* __restrict__ out)
{
    const int b = blockIdx.x;    // batch
    const int l = threadIdx.x;   // lane
    if (g_isgen[b]) { if (l == 0) out[b] = g_gen[b]; return; }

    float va[NCH], vb[NCH];
    #pragma unroll
    for (int c = 0; c < NCH; ++c) {
        va[c] = g_vec[b][c][l];
        vb[c] = g_vec[b][c][l + 32];
    }

    float acc = 0.0f;
    #pragma unroll
    for (int k = 2; k <= KSEG - 1; ++k) {
        float d = va[k + 9] * va[k - 2] + vb[k + 9] * vb[k - 2];
        float s = va[k - 1] + vb[k - 1];
        #pragma unroll
        for (int o = 16; o > 0; o >>= 1) {
            d += __shfl_xor_sync(0xffffffffu, d, o);
            s += __shfl_xor_sync(0xffffffffu, s, o);
        }
        acc += __logf(d) - __logf(s);
    }
    {
        float d = va[NCH - 1] * va[KSEG - 2] + vb[NCH - 1] * vb[KSEG - 2];
        #pragma unroll
        for (int o = 16; o > 0; o >>= 1) d += __shfl_xor_sync(0xffffffffu, d, o);
        acc += __logf(d);
    }

    if (l == 0) {
        int ex = g_ex[b][0] + g_ex[b][NCH - 1];
        #pragma unroll
        for (int c = 11; c <= 20; ++c) ex += g_ex[b][c];
        out[b] = acc + __int2float_rn(ex) * 0.693147180559945f;
    }
}

extern "C" void kernel_launch(void* const* d_in, const int* in_sizes, int n_in,
                              void* d_out, int out_size) {
    const float* logits        = (const float*)d_in[0];
    const float* transitions   = (const float*)d_in[1];
    const float* start_states  = (const float*)d_in[2];
    const float* end_states    = (const float*)d_in[3];
    const int*   mask          = (const int*)d_in[4];
    float* out = (float*)d_out;
    (void)in_sizes; (void)n_in; (void)out_size;

    crf_exp_kernel<<<(NB * LL * TT) / (4 * 256), 256>>>(logits);
    dim3 grid(NB, NCH);
    crf_seg_kernel<<<grid, 128>>>(logits, transitions, start_states,
                                  end_states, mask);
    crf_combine_kernel<<<NB, 32>>>(out);
}